// round 8
// baseline (speedup 1.0000x reference)
#include <cuda_runtime.h>
#include <cuda_fp16.h>
#include <math.h>
#include <stdint.h>

// ---------------------------------------------------------------------------
// Problem constants
// ---------------------------------------------------------------------------
#define Bq   2
#define Sq   1024
#define Hq   4096
#define NH   32
#define NKV  8
#define HD   128
#define Gq   4
#define QKVW 6144
#define FF   16384
#define Mrows (Bq * Sq)
#define EPS  1e-5f
#define ATTN_SCALE 0.08838834764831845f

// ---------------------------------------------------------------------------
// Helpers
// ---------------------------------------------------------------------------
__device__ __forceinline__ uint32_t smem_u32(const void* p) {
    uint32_t a;
    asm("{ .reg .u64 t; cvta.to.shared.u64 t, %1; cvt.u32.u64 %0, t; }" : "=r"(a) : "l"(p));
    return a;
}
#define CP_ASYNC16(dst, src) \
    asm volatile("cp.async.cg.shared.global [%0], [%1], 16;" :: "r"(dst), "l"(src) : "memory")
#define CP_COMMIT() asm volatile("cp.async.commit_group;" ::: "memory")

#define LDSM_X4(r0, r1, r2, r3, addr) \
    asm volatile("ldmatrix.sync.aligned.m8n8.x4.shared.b16 {%0,%1,%2,%3}, [%4];" \
        : "=r"(r0), "=r"(r1), "=r"(r2), "=r"(r3) : "r"(addr))
#define LDSM_X4T(r0, r1, r2, r3, addr) \
    asm volatile("ldmatrix.sync.aligned.m8n8.x4.trans.shared.b16 {%0,%1,%2,%3}, [%4];" \
        : "=r"(r0), "=r"(r1), "=r"(r2), "=r"(r3) : "r"(addr))

__device__ __forceinline__ float gelu_exact(float x) {
    return 0.5f * x * (1.0f + erff(x * 0.7071067811865475f));
}
__device__ __forceinline__ uint32_t h2u(float a, float b) {
    __half2 h = __floats2half2_rn(a, b);
    return *(uint32_t*)&h;
}

// fp16 MMA, f32 accumulate: m16n8k16
__device__ __forceinline__ void mma_f16(float* c, uint32_t a0, uint32_t a1,
                                        uint32_t a2, uint32_t a3,
                                        uint32_t b0, uint32_t b1)
{
    asm volatile(
        "mma.sync.aligned.m16n8k16.row.col.f32.f16.f16.f32 "
        "{%0,%1,%2,%3}, {%4,%5,%6,%7}, {%8,%9}, {%0,%1,%2,%3};"
        : "+f"(c[0]), "+f"(c[1]), "+f"(c[2]), "+f"(c[3])
        : "r"(a0), "r"(a1), "r"(a2), "r"(a3), "r"(b0), "r"(b1));
}

// ---------------------------------------------------------------------------
// Scratch (device globals)
// ---------------------------------------------------------------------------
__device__ __half g_attn_in [Mrows * Hq];
__device__ __half g_mlp_in  [Mrows * Hq];
__device__ __half g_qkv     [Mrows * QKVW];
__device__ __half g_q       [(size_t)Bq * NH  * Sq * HD];
__device__ __half g_k       [(size_t)Bq * NKV * Sq * HD];
__device__ __half g_v       [(size_t)Bq * NKV * Sq * HD];
__device__ __half g_ctx     [Mrows * Hq];
__device__ float  g_attn_out[Mrows * Hq];
__device__ __half g_fc      [(size_t)Mrows * FF];
__device__ __half g_wqkv_t  [(size_t)QKVW * Hq];
__device__ __half g_wdense_t[(size_t)Hq * Hq];
__device__ __half g_wfc_t   [(size_t)FF * Hq];
__device__ __half g_wout_t  [(size_t)Hq * FF];

// ---------------------------------------------------------------------------
// Weight transpose + fp16 round
// ---------------------------------------------------------------------------
__global__ void __launch_bounds__(256)
transpose_h_kernel(const float* __restrict__ W, __half* __restrict__ Wt, int Kd, int Nd)
{
    __shared__ float tile[64][33];
    int n0 = blockIdx.x * 32, k0 = blockIdx.y * 64;
    int tx = threadIdx.x & 31, ty = threadIdx.x >> 5;
    #pragma unroll
    for (int r = 0; r < 64; r += 8)
        tile[ty + r][tx] = W[(size_t)(k0 + ty + r) * Nd + n0 + tx];
    __syncthreads();
    #pragma unroll
    for (int r = 0; r < 32; r += 8) {
        int n = ty + r;
        __half2 h = __floats2half2_rn(tile[tx * 2][n], tile[tx * 2 + 1][n]);
        *(__half2*)&Wt[(size_t)(n0 + n) * Kd + k0 + tx * 2] = h;
    }
}

// ---------------------------------------------------------------------------
// Dual LayerNorm -> fp16 outputs
// ---------------------------------------------------------------------------
__global__ void __launch_bounds__(256)
ln_dual_kernel(const float* __restrict__ x,
               const float* __restrict__ s1, const float* __restrict__ b1,
               const float* __restrict__ s2, const float* __restrict__ b2,
               __half* __restrict__ o1, __half* __restrict__ o2)
{
    int row = blockIdx.x;
    const float4* xr = (const float4*)(x + (size_t)row * Hq);

    float sum = 0.f, sq = 0.f;
    for (int i = threadIdx.x; i < Hq / 4; i += 256) {
        float4 v = xr[i];
        sum += v.x + v.y + v.z + v.w;
        sq  += v.x*v.x + v.y*v.y + v.z*v.z + v.w*v.w;
    }
    #pragma unroll
    for (int o = 16; o; o >>= 1) {
        sum += __shfl_xor_sync(0xFFFFFFFFu, sum, o);
        sq  += __shfl_xor_sync(0xFFFFFFFFu, sq,  o);
    }
    __shared__ float wsum[8], wsq[8];
    int w = threadIdx.x >> 5, l = threadIdx.x & 31;
    if (l == 0) { wsum[w] = sum; wsq[w] = sq; }
    __syncthreads();
    sum = 0.f; sq = 0.f;
    #pragma unroll
    for (int i = 0; i < 8; i++) { sum += wsum[i]; sq += wsq[i]; }

    float mean = sum * (1.0f / Hq);
    float var  = sq  * (1.0f / Hq) - mean * mean;
    float rstd = rsqrtf(var + EPS);

    const float4* s1r = (const float4*)s1;
    const float4* b1r = (const float4*)b1;
    const float4* s2r = (const float4*)s2;
    const float4* b2r = (const float4*)b2;
    __half2* o1r = (__half2*)(o1 + (size_t)row * Hq);
    __half2* o2r = (__half2*)(o2 + (size_t)row * Hq);

    for (int i = threadIdx.x; i < Hq / 4; i += 256) {
        float4 v = xr[i];
        float4 a = s1r[i], c = b1r[i], d = s2r[i], e = b2r[i];
        float nx = (v.x - mean) * rstd;
        float ny = (v.y - mean) * rstd;
        float nz = (v.z - mean) * rstd;
        float nw = (v.w - mean) * rstd;
        o1r[2*i]   = __floats2half2_rn(nx*a.x + c.x, ny*a.y + c.y);
        o1r[2*i+1] = __floats2half2_rn(nz*a.z + c.z, nw*a.w + c.w);
        o2r[2*i]   = __floats2half2_rn(nx*d.x + e.x, ny*d.y + e.y);
        o2r[2*i+1] = __floats2half2_rn(nz*d.z + e.z, nw*d.w + e.w);
    }
}

// ---------------------------------------------------------------------------
// fp16 mma.sync GEMM core: C[M,N] = A[M,K] @ Bt[N,K]^T
// 256x128x32 CTA tile, 8 warps (4m x 2n), warp 64x64, ldmatrix fragments,
// 5-stage cp.async ring.
// epi: 0 f32 out, 1 GELU->fp16 out, 2 +R1+R2 f32 out, 3 fp16 out
// ---------------------------------------------------------------------------
#define SROW 40
#define GSTG 5
#define ASZ  (256 * SROW)
#define BSZ  (128 * SROW)
#define STGSZ (ASZ + BSZ)
#define GEMM_SMEM (GSTG * STGSZ * 2)   // 153600 bytes

__device__ __forceinline__ void g_load(const __half* __restrict__ Ag,
                                       const __half* __restrict__ Bg, int K,
                                       __half* stage, int k0, int tid)
{
    __half* As = stage;
    __half* Bs = stage + ASZ;
    int c8 = (tid & 3) * 8;
    int rA = tid >> 2;
    #pragma unroll
    for (int j = 0; j < 4; j++) {
        int r = rA + j * 64;
        CP_ASYNC16(smem_u32(&As[r * SROW + c8]), Ag + (size_t)r * K + k0 + c8);
    }
    #pragma unroll
    for (int j = 0; j < 2; j++) {
        int r = rA + j * 64;
        CP_ASYNC16(smem_u32(&Bs[r * SROW + c8]), Bg + (size_t)r * K + k0 + c8);
    }
    CP_COMMIT();
}

__device__ __forceinline__ void gemm_core(const __half* __restrict__ A,
                                          const __half* __restrict__ Bt,
                                          void* __restrict__ Cv, int K, int N,
                                          int epi,
                                          const float* __restrict__ R1,
                                          const float* __restrict__ R2,
                                          int m0, int n0, __half* gsm)
{
    int tid = threadIdx.x;
    int lane = tid & 31;
    int wid = tid >> 5;
    int wm = (wid & 3) * 64;
    int wn = (wid >> 2) * 64;
    int lr = lane >> 2;
    int lc = lane & 3;

    const __half* Ag = A  + (size_t)m0 * K;
    const __half* Bg = Bt + (size_t)n0 * K;

    float acc[4][8][4];
    #pragma unroll
    for (int i = 0; i < 4; i++)
        #pragma unroll
        for (int j = 0; j < 8; j++)
            #pragma unroll
            for (int q = 0; q < 4; q++) acc[i][j][q] = 0.f;

    const int NC = K / 32;
    g_load(Ag, Bg, K, gsm + 0 * STGSZ,  0, tid);
    g_load(Ag, Bg, K, gsm + 1 * STGSZ, 32, tid);
    g_load(Ag, Bg, K, gsm + 2 * STGSZ, 64, tid);
    g_load(Ag, Bg, K, gsm + 3 * STGSZ, 96, tid);

    int cur = 0;
    int aoff = (lane & 15) * SROW + (lane >> 4) * 8;   // ldmatrix lane addressing

    for (int c = 0; c < NC; c++) {
        if (c + 3 < NC) asm volatile("cp.async.wait_group 3;" ::: "memory");
        else            asm volatile("cp.async.wait_group 0;" ::: "memory");
        __syncthreads();

        if (c + 4 < NC) {
            int pf = (cur == 0) ? 4 : cur - 1;      // (cur+4) % 5
            g_load(Ag, Bg, K, gsm + pf * STGSZ, (c + 4) * 32, tid);
        }

        const __half* Ast = gsm + cur * STGSZ;
        const __half* Bst = Ast + ASZ;

        #pragma unroll
        for (int ks = 0; ks < 2; ks++) {
            int ko = ks * 16;
            uint32_t af[4][4];
            #pragma unroll
            for (int i = 0; i < 4; i++) {
                uint32_t addr = smem_u32(&Ast[(wm + i * 16) * SROW + ko + aoff]);
                LDSM_X4(af[i][0], af[i][1], af[i][2], af[i][3], addr);
            }
            #pragma unroll
            for (int jj = 0; jj < 4; jj++) {
                uint32_t b0, b1, b2, b3;
                uint32_t addr = smem_u32(&Bst[(wn + jj * 16) * SROW + ko + aoff]);
                LDSM_X4(b0, b1, b2, b3, addr);
                #pragma unroll
                for (int i = 0; i < 4; i++) {
                    mma_f16(acc[i][2 * jj],     af[i][0], af[i][1], af[i][2], af[i][3], b0, b2);
                    mma_f16(acc[i][2 * jj + 1], af[i][0], af[i][1], af[i][2], af[i][3], b1, b3);
                }
            }
        }
        cur = (cur == 4) ? 0 : cur + 1;
    }

    #pragma unroll
    for (int i = 0; i < 4; i++) {
        #pragma unroll
        for (int j = 0; j < 8; j++) {
            int r0 = m0 + wm + i * 16 + lr;
            int cc = n0 + wn + j * 8 + lc * 2;
            float x0 = acc[i][j][0], x1 = acc[i][j][1];
            float x2 = acc[i][j][2], x3 = acc[i][j][3];
            if (epi == 1) {
                __half* Ch = (__half*)Cv;
                *(__half2*)(Ch + (size_t)r0 * N + cc) =
                    __floats2half2_rn(gelu_exact(x0), gelu_exact(x1));
                *(__half2*)(Ch + (size_t)(r0 + 8) * N + cc) =
                    __floats2half2_rn(gelu_exact(x2), gelu_exact(x3));
            } else if (epi == 3) {
                __half* Ch = (__half*)Cv;
                *(__half2*)(Ch + (size_t)r0 * N + cc)       = __floats2half2_rn(x0, x1);
                *(__half2*)(Ch + (size_t)(r0 + 8) * N + cc) = __floats2half2_rn(x2, x3);
            } else {
                float* Cf = (float*)Cv;
                if (epi == 2) {
                    size_t i0 = (size_t)r0 * N + cc;
                    size_t i1 = (size_t)(r0 + 8) * N + cc;
                    float2 a0 = *(const float2*)(R1 + i0);
                    float2 a1 = *(const float2*)(R1 + i1);
                    float2 d0 = *(const float2*)(R2 + i0);
                    float2 d1 = *(const float2*)(R2 + i1);
                    x0 += a0.x + d0.x; x1 += a0.y + d0.y;
                    x2 += a1.x + d1.x; x3 += a1.y + d1.y;
                }
                *(float2*)(Cf + (size_t)r0 * N + cc)       = make_float2(x0, x1);
                *(float2*)(Cf + (size_t)(r0 + 8) * N + cc) = make_float2(x2, x3);
            }
        }
    }
}

// Single-job GEMM: grid (Mrows/256, N/128)
__global__ void __launch_bounds__(256, 1)
mma_gemm_kernel(const __half* __restrict__ A, const __half* __restrict__ Bt,
                void* __restrict__ Cv, int K, int N, int epi,
                const float* __restrict__ R1, const float* __restrict__ R2)
{
    extern __shared__ __half gsm[];
    gemm_core(A, Bt, Cv, K, N, epi, R1, R2, blockIdx.x * 256, blockIdx.y * 128, gsm);
}

// Dual-job GEMM (independent jobs, same M=2048): flattened 1D grid.
// Job0 occupies indices [0, nx0); job1 the rest. m0 = (idx & 7) * 256.
__global__ void __launch_bounds__(256, 1)
mma_gemm_dual(const __half* __restrict__ A0, const __half* __restrict__ B0,
              void* __restrict__ C0, int K0, int N0, int epi0, int nx0,
              const __half* __restrict__ A1, const __half* __restrict__ B1,
              void* __restrict__ C1, int K1, int N1, int epi1)
{
    extern __shared__ __half gsm[];
    int idx = blockIdx.x;
    if (idx < nx0) {
        gemm_core(A0, B0, C0, K0, N0, epi0, nullptr, nullptr,
                  (idx & 7) * 256, (idx >> 3) * 128, gsm);
    } else {
        idx -= nx0;
        gemm_core(A1, B1, C1, K1, N1, epi1, nullptr, nullptr,
                  (idx & 7) * 256, (idx >> 3) * 128, gsm);
    }
}

// ---------------------------------------------------------------------------
// RoPE + head split (fp16 in/out)
// ---------------------------------------------------------------------------
__global__ void __launch_bounds__(128)
rope_kernel(const __half* __restrict__ qkv,
            const float* __restrict__ sint, const float* __restrict__ cost,
            const int* __restrict__ pos_ids,
            __half* __restrict__ Qo, __half* __restrict__ Ko, __half* __restrict__ Vo)
{
    int d = threadIdx.x;
    int idx = blockIdx.x;
    int kvh = idx % NKV; idx /= NKV;
    int s = idx % Sq;
    int b = idx / Sq;

    int pos = pos_ids[b * Sq + s];
    float sn = sint[pos * HD + d];
    float cs = cost[pos * HD + d];
    int dro = (d < 64) ? (d + 64) : (d - 64);
    float sgn = (d < 64) ? -1.f : 1.f;

    const __half* base = qkv + (size_t)(b * Sq + s) * QKVW + kvh * (Gq + 2) * HD;

    float kx = __half2float(base[Gq * HD + d]);
    float ko = __half2float(base[Gq * HD + dro]);
    size_t kvidx = ((size_t)(b * NKV + kvh) * Sq + s) * HD + d;
    Ko[kvidx] = __float2half_rn(kx * cs + sgn * ko * sn);
    Vo[kvidx] = base[(Gq + 1) * HD + d];

    #pragma unroll
    for (int g = 0; g < Gq; g++) {
        int h = kvh * Gq + g;
        float qx = __half2float(base[g * HD + d]);
        float qo = __half2float(base[g * HD + dro]);
        Qo[((size_t)(b * NH + h) * Sq + s) * HD + d] =
            __float2half_rn(qx * cs + sgn * qo * sn);
    }
}

// ---------------------------------------------------------------------------
// Tensor-core flash attention, cp.async double-buffered K/V pipeline.
// ---------------------------------------------------------------------------
#define VROW 136
#define KVSZ (64 * VROW)
#define ATTN_SMEM (5 * KVSZ * 2 + 2 * 64 * 4)

__device__ __forceinline__ void kv_load(const __half* __restrict__ Kb,
                                        const __half* __restrict__ Vb,
                                        __half* Ks, __half* Vs, int k0, int t)
{
    #pragma unroll
    for (int j = 0; j < 8; j++) {
        int i = t + j * 128;
        int r = i >> 4, c8 = (i & 15) * 8;
        CP_ASYNC16(smem_u32(&Ks[r * VROW + c8]), Kb + (size_t)(k0 + r) * HD + c8);
        CP_ASYNC16(smem_u32(&Vs[r * VROW + c8]), Vb + (size_t)(k0 + r) * HD + c8);
    }
    CP_COMMIT();
}

__global__ void __launch_bounds__(128)
attn_kernel(const __half* __restrict__ Q, const __half* __restrict__ Kg,
            const __half* __restrict__ Vg, const int* __restrict__ amask,
            __half* __restrict__ ctx)
{
    extern __shared__ __half asmem[];
    __half* Qs = asmem;
    __half* Kst0 = asmem + KVSZ;
    __half* Vst0 = asmem + 2 * KVSZ;
    __half* Kst1 = asmem + 3 * KVSZ;
    __half* Vst1 = asmem + 4 * KVSZ;
    int* smask = (int*)(asmem + 5 * KVSZ);   // [2][64]

    int t = threadIdx.x, lane = t & 31, w = t >> 5;
    int q0 = blockIdx.x * 64, h = blockIdx.y, b = blockIdx.z, kv = h >> 2;
    int lr = lane >> 2, lc = lane & 3;

    const __half* Qb = Q  + ((size_t)(b * NH  + h ) * Sq + q0) * HD;
    const __half* Kb = Kg + ((size_t)(b * NKV + kv) * Sq) * HD;
    const __half* Vb = Vg + ((size_t)(b * NKV + kv) * Sq) * HD;

    const int nc = q0 / 64 + 1;

    kv_load(Kb, Vb, Kst0, Vst0, 0, t);
    if (t < 64) smask[t] = amask[b * Sq + t];

    for (int i = t; i < 64 * 16; i += 128) {
        int r = i >> 4, c8 = (i & 15) * 8;
        *(uint4*)&Qs[r * VROW + c8] = *(const uint4*)(Qb + (size_t)r * HD + c8);
    }
    __syncthreads();

    uint32_t qf[8][4];
    #pragma unroll
    for (int kk = 0; kk < 8; kk++) {
        uint32_t addr = smem_u32(&Qs[(16 * w + (lane & 15)) * VROW + kk * 16 + (lane >> 4) * 8]);
        LDSM_X4(qf[kk][0], qf[kk][1], qf[kk][2], qf[kk][3], addr);
    }

    float oacc[16][4];
    #pragma unroll
    for (int i = 0; i < 16; i++)
        #pragma unroll
        for (int q = 0; q < 4; q++) oacc[i][q] = 0.f;

    float m0r = -1e30f, m1r = -1e30f, l0r = 0.f, l1r = 0.f;
    int qg1 = q0 + 16 * w + lr, qg2 = qg1 + 8;

    for (int c = 0; c < nc; c++) {
        int st = c & 1;
        __half* Ks = st ? Kst1 : Kst0;
        __half* Vs = st ? Vst1 : Vst0;
        const int* msk = smask + st * 64;
        int k0 = c * 64;

        if (c + 1 < nc) {
            kv_load(Kb, Vb, st ? Kst0 : Kst1, st ? Vst0 : Vst1, k0 + 64, t);
            if (t < 64) smask[(st ^ 1) * 64 + t] = amask[b * Sq + k0 + 64 + t];
            asm volatile("cp.async.wait_group 1;" ::: "memory");
        } else {
            asm volatile("cp.async.wait_group 0;" ::: "memory");
        }
        __syncthreads();

        float sacc[8][4];
        #pragma unroll
        for (int j = 0; j < 8; j++)
            #pragma unroll
            for (int q = 0; q < 4; q++) sacc[j][q] = 0.f;

        #pragma unroll
        for (int kk = 0; kk < 8; kk++) {
            #pragma unroll
            for (int jj = 0; jj < 4; jj++) {
                uint32_t addr = smem_u32(&Ks[(16 * jj + (lane & 7) + (lane >> 4) * 8) * VROW
                                             + kk * 16 + ((lane >> 3) & 1) * 8]);
                uint32_t b0, b1, b2, b3;
                LDSM_X4(b0, b1, b2, b3, addr);
                mma_f16(sacc[2 * jj],     qf[kk][0], qf[kk][1], qf[kk][2], qf[kk][3], b0, b1);
                mma_f16(sacc[2 * jj + 1], qf[kk][0], qf[kk][1], qf[kk][2], qf[kk][3], b2, b3);
            }
        }

        float mn0 = m0r, mn1 = m1r;
        #pragma unroll
        for (int j = 0; j < 8; j++) {
            int kg = k0 + 8 * j + 2 * lc;
            bool ma = msk[8 * j + 2 * lc] > 0;
            bool mb = msk[8 * j + 2 * lc + 1] > 0;
            float s0 = (ma && kg     <= qg1) ? sacc[j][0] * ATTN_SCALE : -1e30f;
            float s1 = (mb && kg + 1 <= qg1) ? sacc[j][1] * ATTN_SCALE : -1e30f;
            float s2 = (ma && kg     <= qg2) ? sacc[j][2] * ATTN_SCALE : -1e30f;
            float s3 = (mb && kg + 1 <= qg2) ? sacc[j][3] * ATTN_SCALE : -1e30f;
            sacc[j][0] = s0; sacc[j][1] = s1; sacc[j][2] = s2; sacc[j][3] = s3;
            mn0 = fmaxf(mn0, fmaxf(s0, s1));
            mn1 = fmaxf(mn1, fmaxf(s2, s3));
        }
        mn0 = fmaxf(mn0, __shfl_xor_sync(0xFFFFFFFFu, mn0, 1));
        mn0 = fmaxf(mn0, __shfl_xor_sync(0xFFFFFFFFu, mn0, 2));
        mn1 = fmaxf(mn1, __shfl_xor_sync(0xFFFFFFFFu, mn1, 1));
        mn1 = fmaxf(mn1, __shfl_xor_sync(0xFFFFFFFFu, mn1, 2));

        float cf0 = __expf(m0r - mn0);
        float cf1 = __expf(m1r - mn1);
        m0r = mn0; m1r = mn1;

        uint32_t pf[8][2];
        float la0 = 0.f, la1 = 0.f;
        #pragma unroll
        for (int j = 0; j < 8; j++) {
            float p0 = __expf(sacc[j][0] - mn0);
            float p1 = __expf(sacc[j][1] - mn0);
            float p2 = __expf(sacc[j][2] - mn1);
            float p3 = __expf(sacc[j][3] - mn1);
            la0 += p0 + p1; la1 += p2 + p3;
            pf[j][0] = h2u(p0, p1);
            pf[j][1] = h2u(p2, p3);
        }
        la0 += __shfl_xor_sync(0xFFFFFFFFu, la0, 1);
        la0 += __shfl_xor_sync(0xFFFFFFFFu, la0, 2);
        la1 += __shfl_xor_sync(0xFFFFFFFFu, la1, 1);
        la1 += __shfl_xor_sync(0xFFFFFFFFu, la1, 2);
        l0r = l0r * cf0 + la0;
        l1r = l1r * cf1 + la1;

        #pragma unroll
        for (int dt = 0; dt < 16; dt++) {
            oacc[dt][0] *= cf0; oacc[dt][1] *= cf0;
            oacc[dt][2] *= cf1; oacc[dt][3] *= cf1;
        }

        #pragma unroll
        for (int t4 = 0; t4 < 4; t4++) {
            uint32_t a0 = pf[2 * t4][0], a1 = pf[2 * t4][1];
            uint32_t a2 = pf[2 * t4 + 1][0], a3 = pf[2 * t4 + 1][1];
            #pragma unroll
            for (int jn2 = 0; jn2 < 8; jn2++) {
                uint32_t addr = smem_u32(&Vs[(16 * t4 + (lane & 7) + ((lane >> 3) & 1) * 8) * VROW
                                             + 16 * jn2 + (lane >> 4) * 8]);
                uint32_t v0, v1, v2, v3;
                LDSM_X4T(v0, v1, v2, v3, addr);
                mma_f16(oacc[2 * jn2],     a0, a1, a2, a3, v0, v1);
                mma_f16(oacc[2 * jn2 + 1], a0, a1, a2, a3, v2, v3);
            }
        }
        __syncthreads();
    }

    float inv0 = 1.f / l0r, inv1 = 1.f / l1r;
    int row1 = q0 + 16 * w + lr, row2 = row1 + 8;
    #pragma unroll
    for (int jn = 0; jn < 16; jn++) {
        int col = h * HD + 8 * jn + 2 * lc;
        *(__half2*)&ctx[(size_t)(b * Sq + row1) * Hq + col] =
            __floats2half2_rn(oacc[jn][0] * inv0, oacc[jn][1] * inv0);
        *(__half2*)&ctx[(size_t)(b * Sq + row2) * Hq + col] =
            __floats2half2_rn(oacc[jn][2] * inv1, oacc[jn][3] * inv1);
    }
}

// ---------------------------------------------------------------------------
// Launch
// ---------------------------------------------------------------------------
extern "C" void kernel_launch(void* const* d_in, const int* in_sizes, int n_in,
                              void* d_out, int out_size)
{
    const float* hidden  = (const float*)d_in[0];
    const float* w_qkv   = (const float*)d_in[1];
    const float* w_dense = (const float*)d_in[2];
    const float* ln_a_s  = (const float*)d_in[3];
    const float* ln_a_b  = (const float*)d_in[4];
    const float* ln_m_s  = (const float*)d_in[5];
    const float* ln_m_b  = (const float*)d_in[6];
    const float* w_fc    = (const float*)d_in[7];
    const float* w_out   = (const float*)d_in[8];
    const float* sin_tab = (const float*)d_in[9];
    const float* cos_tab = (const float*)d_in[10];
    const int*   amask   = (const int*)d_in[11];
    const int*   pos_ids = (const int*)d_in[12];
    float* out = (float*)d_out;

    __half *p_attn_in, *p_mlp_in, *p_qkv, *p_q, *p_k, *p_v, *p_ctx, *p_fc;
    __half *p_wqkv, *p_wdense, *p_wfc, *p_wout;
    float *p_attn_out;
    cudaGetSymbolAddress((void**)&p_attn_in,  g_attn_in);
    cudaGetSymbolAddress((void**)&p_mlp_in,   g_mlp_in);
    cudaGetSymbolAddress((void**)&p_qkv,      g_qkv);
    cudaGetSymbolAddress((void**)&p_q,        g_q);
    cudaGetSymbolAddress((void**)&p_k,        g_k);
    cudaGetSymbolAddress((void**)&p_v,        g_v);
    cudaGetSymbolAddress((void**)&p_ctx,      g_ctx);
    cudaGetSymbolAddress((void**)&p_attn_out, g_attn_out);
    cudaGetSymbolAddress((void**)&p_fc,       g_fc);
    cudaGetSymbolAddress((void**)&p_wqkv,     g_wqkv_t);
    cudaGetSymbolAddress((void**)&p_wdense,   g_wdense_t);
    cudaGetSymbolAddress((void**)&p_wfc,      g_wfc_t);
    cudaGetSymbolAddress((void**)&p_wout,     g_wout_t);

    cudaFuncSetAttribute(mma_gemm_kernel, cudaFuncAttributeMaxDynamicSharedMemorySize, GEMM_SMEM);
    cudaFuncSetAttribute(mma_gemm_dual,   cudaFuncAttributeMaxDynamicSharedMemorySize, GEMM_SMEM);
    cudaFuncSetAttribute(attn_kernel,     cudaFuncAttributeMaxDynamicSharedMemorySize, ATTN_SMEM);

    // 0. transpose + fp16-round weights into [N,K]
    transpose_h_kernel<<<dim3(QKVW/32, Hq/64), 256>>>(w_qkv,   p_wqkv,   Hq, QKVW);
    transpose_h_kernel<<<dim3(Hq/32,   Hq/64), 256>>>(w_dense, p_wdense, Hq, Hq);
    transpose_h_kernel<<<dim3(FF/32,   Hq/64), 256>>>(w_fc,    p_wfc,    Hq, FF);
    transpose_h_kernel<<<dim3(Hq/32,   FF/64), 256>>>(w_out,   p_wout,   FF, Hq);

    // 1. parallel layernorms (fp16 outputs)
    ln_dual_kernel<<<Mrows, 256>>>(hidden, ln_a_s, ln_a_b, ln_m_s, ln_m_b,
                                   p_attn_in, p_mlp_in);

    // 2. qkv projection (fp16 out)
    mma_gemm_kernel<<<dim3(Mrows/256, QKVW/128), 256, GEMM_SMEM>>>(
        p_attn_in, p_wqkv, p_qkv, Hq, QKVW, 3, nullptr, nullptr);

    // 3. rope + head split (fp16)
    rope_kernel<<<Bq * Sq * NKV, 128>>>(p_qkv, sin_tab, cos_tab, pos_ids,
                                        p_q, p_k, p_v);

    // 4. tensor-core attention, pipelined (ctx fp16)
    attn_kernel<<<dim3(Sq / 64, NH, Bq), 128, ATTN_SMEM>>>(
        p_q, p_k, p_v, amask, p_ctx);

    // 5+6. dense projection (f32 out) + MLP fc with GELU (fp16 out), merged
    {
        int nx_dense = (Mrows / 256) * (Hq / 128);   // 256
        int nx_fc    = (Mrows / 256) * (FF / 128);   // 1024
        mma_gemm_dual<<<nx_dense + nx_fc, 256, GEMM_SMEM>>>(
            p_ctx,    p_wdense, p_attn_out, Hq, Hq, 0, nx_dense,
            p_mlp_in, p_wfc,    p_fc,       Hq, FF, 1);
    }

    // 7. MLP out + parallel residual -> d_out (f32)
    mma_gemm_kernel<<<dim3(Mrows/256, Hq/128), 256, GEMM_SMEM>>>(
        p_fc, p_wout, out, FF, Hq, 2, hidden, p_attn_out);
}

// round 9
// speedup vs baseline: 1.0529x; 1.0529x over previous
#include <cuda_runtime.h>
#include <cuda_fp16.h>
#include <math.h>
#include <stdint.h>

// ---------------------------------------------------------------------------
// Problem constants
// ---------------------------------------------------------------------------
#define Bq   2
#define Sq   1024
#define Hq   4096
#define NH   32
#define NKV  8
#define HD   128
#define Gq   4
#define QKVW 6144
#define FF   16384
#define Mrows (Bq * Sq)
#define EPS  1e-5f
#define ATTN_SCALE 0.08838834764831845f

// ---------------------------------------------------------------------------
// Helpers
// ---------------------------------------------------------------------------
__device__ __forceinline__ uint32_t smem_u32(const void* p) {
    uint32_t a;
    asm("{ .reg .u64 t; cvta.to.shared.u64 t, %1; cvt.u32.u64 %0, t; }" : "=r"(a) : "l"(p));
    return a;
}
#define CP_ASYNC16(dst, src) \
    asm volatile("cp.async.cg.shared.global [%0], [%1], 16;" :: "r"(dst), "l"(src) : "memory")
#define CP_COMMIT() asm volatile("cp.async.commit_group;" ::: "memory")

#define LDSM_X4(r0, r1, r2, r3, addr) \
    asm volatile("ldmatrix.sync.aligned.m8n8.x4.shared.b16 {%0,%1,%2,%3}, [%4];" \
        : "=r"(r0), "=r"(r1), "=r"(r2), "=r"(r3) : "r"(addr))
#define LDSM_X4T(r0, r1, r2, r3, addr) \
    asm volatile("ldmatrix.sync.aligned.m8n8.x4.trans.shared.b16 {%0,%1,%2,%3}, [%4];" \
        : "=r"(r0), "=r"(r1), "=r"(r2), "=r"(r3) : "r"(addr))

__device__ __forceinline__ float gelu_exact(float x) {
    return 0.5f * x * (1.0f + erff(x * 0.7071067811865475f));
}
__device__ __forceinline__ uint32_t h2u(float a, float b) {
    __half2 h = __floats2half2_rn(a, b);
    return *(uint32_t*)&h;
}

// fp16 MMA, f32 accumulate: m16n8k16
__device__ __forceinline__ void mma_f16(float* c, uint32_t a0, uint32_t a1,
                                        uint32_t a2, uint32_t a3,
                                        uint32_t b0, uint32_t b1)
{
    asm volatile(
        "mma.sync.aligned.m16n8k16.row.col.f32.f16.f16.f32 "
        "{%0,%1,%2,%3}, {%4,%5,%6,%7}, {%8,%9}, {%0,%1,%2,%3};"
        : "+f"(c[0]), "+f"(c[1]), "+f"(c[2]), "+f"(c[3])
        : "r"(a0), "r"(a1), "r"(a2), "r"(a3), "r"(b0), "r"(b1));
}

// ---------------------------------------------------------------------------
// Scratch (device globals)
// ---------------------------------------------------------------------------
__device__ __half g_attn_in [Mrows * Hq];
__device__ __half g_mlp_in  [Mrows * Hq];
__device__ __half g_qkv     [Mrows * QKVW];
__device__ __half g_q       [(size_t)Bq * NH  * Sq * HD];
__device__ __half g_k       [(size_t)Bq * NKV * Sq * HD];
__device__ __half g_v       [(size_t)Bq * NKV * Sq * HD];
__device__ __half g_ctx     [Mrows * Hq];
__device__ float  g_attn_out[Mrows * Hq];
__device__ __half g_fc      [(size_t)Mrows * FF];
__device__ __half g_wqkv_t  [(size_t)QKVW * Hq];
__device__ __half g_wdense_t[(size_t)Hq * Hq];
__device__ __half g_wfc_t   [(size_t)FF * Hq];
__device__ __half g_wout_t  [(size_t)Hq * FF];

// ---------------------------------------------------------------------------
// Merged weight transpose + fp16 round: all 4 weights in one launch.
// Per job: Wt[n,k] = half(W[k,n]); 64k x 32n tiles.
// ---------------------------------------------------------------------------
#define TR_NB0 12288                     // qkv:   (6144/32)*(4096/64)
#define TR_NB1 (TR_NB0 + 8192)           // dense: (4096/32)*(4096/64)
#define TR_NB2 (TR_NB1 + 32768)          // fc:    (16384/32)*(4096/64)
#define TR_NB3 (TR_NB2 + 32768)          // out:   (4096/32)*(16384/64)

__global__ void __launch_bounds__(256)
transpose4_kernel(const float* __restrict__ W0, __half* __restrict__ T0,
                  const float* __restrict__ W1, __half* __restrict__ T1,
                  const float* __restrict__ W2, __half* __restrict__ T2,
                  const float* __restrict__ W3, __half* __restrict__ T3)
{
    int idx = blockIdx.x;
    const float* W; __half* Wt; int Kd, Nd;
    if (idx < TR_NB0)      { W = W0; Wt = T0; Kd = Hq; Nd = QKVW; }
    else if (idx < TR_NB1) { W = W1; Wt = T1; Kd = Hq; Nd = Hq;   idx -= TR_NB0; }
    else if (idx < TR_NB2) { W = W2; Wt = T2; Kd = Hq; Nd = FF;   idx -= TR_NB1; }
    else                   { W = W3; Wt = T3; Kd = FF; Nd = Hq;   idx -= TR_NB2; }
    int nx = Nd / 32;
    int n0 = (idx % nx) * 32, k0 = (idx / nx) * 64;

    __shared__ float tile[64][33];
    int tx = threadIdx.x & 31, ty = threadIdx.x >> 5;
    #pragma unroll
    for (int r = 0; r < 64; r += 8)
        tile[ty + r][tx] = W[(size_t)(k0 + ty + r) * Nd + n0 + tx];
    __syncthreads();
    #pragma unroll
    for (int r = 0; r < 32; r += 8) {
        int n = ty + r;
        __half2 h = __floats2half2_rn(tile[tx * 2][n], tile[tx * 2 + 1][n]);
        *(__half2*)&Wt[(size_t)(n0 + n) * Kd + k0 + tx * 2] = h;
    }
}

// ---------------------------------------------------------------------------
// Dual LayerNorm -> fp16 outputs
// ---------------------------------------------------------------------------
__global__ void __launch_bounds__(256)
ln_dual_kernel(const float* __restrict__ x,
               const float* __restrict__ s1, const float* __restrict__ b1,
               const float* __restrict__ s2, const float* __restrict__ b2,
               __half* __restrict__ o1, __half* __restrict__ o2)
{
    int row = blockIdx.x;
    const float4* xr = (const float4*)(x + (size_t)row * Hq);

    float sum = 0.f, sq = 0.f;
    for (int i = threadIdx.x; i < Hq / 4; i += 256) {
        float4 v = xr[i];
        sum += v.x + v.y + v.z + v.w;
        sq  += v.x*v.x + v.y*v.y + v.z*v.z + v.w*v.w;
    }
    #pragma unroll
    for (int o = 16; o; o >>= 1) {
        sum += __shfl_xor_sync(0xFFFFFFFFu, sum, o);
        sq  += __shfl_xor_sync(0xFFFFFFFFu, sq,  o);
    }
    __shared__ float wsum[8], wsq[8];
    int w = threadIdx.x >> 5, l = threadIdx.x & 31;
    if (l == 0) { wsum[w] = sum; wsq[w] = sq; }
    __syncthreads();
    sum = 0.f; sq = 0.f;
    #pragma unroll
    for (int i = 0; i < 8; i++) { sum += wsum[i]; sq += wsq[i]; }

    float mean = sum * (1.0f / Hq);
    float var  = sq  * (1.0f / Hq) - mean * mean;
    float rstd = rsqrtf(var + EPS);

    const float4* s1r = (const float4*)s1;
    const float4* b1r = (const float4*)b1;
    const float4* s2r = (const float4*)s2;
    const float4* b2r = (const float4*)b2;
    __half2* o1r = (__half2*)(o1 + (size_t)row * Hq);
    __half2* o2r = (__half2*)(o2 + (size_t)row * Hq);

    for (int i = threadIdx.x; i < Hq / 4; i += 256) {
        float4 v = xr[i];
        float4 a = s1r[i], c = b1r[i], d = s2r[i], e = b2r[i];
        float nx = (v.x - mean) * rstd;
        float ny = (v.y - mean) * rstd;
        float nz = (v.z - mean) * rstd;
        float nw = (v.w - mean) * rstd;
        o1r[2*i]   = __floats2half2_rn(nx*a.x + c.x, ny*a.y + c.y);
        o1r[2*i+1] = __floats2half2_rn(nz*a.z + c.z, nw*a.w + c.w);
        o2r[2*i]   = __floats2half2_rn(nx*d.x + e.x, ny*d.y + e.y);
        o2r[2*i+1] = __floats2half2_rn(nz*d.z + e.z, nw*d.w + e.w);
    }
}

// ---------------------------------------------------------------------------
// fp16 mma.sync GEMM core (exact R7 winner): C[M,N] = A[M,K] @ Bt[N,K]^T
// 256x128x32 CTA tile, 8 warps (4m x 2n), warp 64x64 (4x8 m16n8k16).
// 4-stage cp.async ring, one __syncthreads per chunk, scalar LDS fragments.
// EPI: 0 f32 out, 1 GELU->fp16 out, 2 +R1+R2 f32 out, 3 fp16 out
// ---------------------------------------------------------------------------
#define SROW 40
#define GSTG 4
#define ASZ  (256 * SROW)
#define BSZ  (128 * SROW)
#define GEMM_SMEM (GSTG * (ASZ + BSZ) * 2)

__device__ __forceinline__ void g_load(const __half* __restrict__ Ag,
                                       const __half* __restrict__ Bg, int K,
                                       __half* As, __half* Bs, int k0, int tid)
{
    int c8 = (tid & 3) * 8;
    int rA = tid >> 2;
    #pragma unroll
    for (int j = 0; j < 4; j++) {
        int r = rA + j * 64;
        CP_ASYNC16(smem_u32(&As[r * SROW + c8]), Ag + (size_t)r * K + k0 + c8);
    }
    #pragma unroll
    for (int j = 0; j < 2; j++) {
        int r = rA + j * 64;
        CP_ASYNC16(smem_u32(&Bs[r * SROW + c8]), Bg + (size_t)r * K + k0 + c8);
    }
    CP_COMMIT();
}

template <int EPI>
__device__ __forceinline__ void gemm_core(const __half* __restrict__ A,
                                          const __half* __restrict__ Bt,
                                          void* __restrict__ Cv, int K, int N,
                                          const float* __restrict__ R1,
                                          const float* __restrict__ R2,
                                          int m0, int n0, __half* gsm)
{
    __half* AsB = gsm;
    __half* BsB = gsm + GSTG * ASZ;

    int tid = threadIdx.x;
    int lane = tid & 31;
    int wid = tid >> 5;
    int wm = (wid & 3) * 64;
    int wn = (wid >> 2) * 64;
    int lr = lane >> 2;
    int lc = lane & 3;

    const __half* Ag = A  + (size_t)m0 * K;
    const __half* Bg = Bt + (size_t)n0 * K;

    float acc[4][8][4];
    #pragma unroll
    for (int i = 0; i < 4; i++)
        #pragma unroll
        for (int j = 0; j < 8; j++)
            #pragma unroll
            for (int q = 0; q < 4; q++) acc[i][j][q] = 0.f;

    const int NC = K / 32;
    g_load(Ag, Bg, K, AsB + 0 * ASZ, BsB + 0 * BSZ,  0, tid);
    g_load(Ag, Bg, K, AsB + 1 * ASZ, BsB + 1 * BSZ, 32, tid);
    g_load(Ag, Bg, K, AsB + 2 * ASZ, BsB + 2 * BSZ, 64, tid);

    for (int c = 0; c < NC; c++) {
        if (c + 2 < NC) asm volatile("cp.async.wait_group 2;" ::: "memory");
        else            asm volatile("cp.async.wait_group 0;" ::: "memory");
        __syncthreads();

        if (c + 3 < NC)
            g_load(Ag, Bg, K, AsB + ((c + 3) & 3) * ASZ, BsB + ((c + 3) & 3) * BSZ,
                   (c + 3) * 32, tid);

        const __half* Ast = AsB + (c & 3) * ASZ;
        const __half* Bst = BsB + (c & 3) * BSZ;

        #pragma unroll
        for (int ks = 0; ks < 2; ks++) {
            int ko = ks * 16;
            uint32_t af[4][4];
            #pragma unroll
            for (int i = 0; i < 4; i++) {
                const __half* ab = &Ast[(wm + i * 16 + lr) * SROW + ko + lc * 2];
                af[i][0] = *(const uint32_t*)(ab);
                af[i][1] = *(const uint32_t*)(ab + 8 * SROW);
                af[i][2] = *(const uint32_t*)(ab + 8);
                af[i][3] = *(const uint32_t*)(ab + 8 * SROW + 8);
            }
            #pragma unroll
            for (int j = 0; j < 8; j++) {
                const __half* bb = &Bst[(wn + j * 8 + lr) * SROW + ko + lc * 2];
                uint32_t b0 = *(const uint32_t*)(bb);
                uint32_t b1 = *(const uint32_t*)(bb + 8);
                #pragma unroll
                for (int i = 0; i < 4; i++)
                    mma_f16(acc[i][j], af[i][0], af[i][1], af[i][2], af[i][3], b0, b1);
            }
        }
    }

    #pragma unroll
    for (int i = 0; i < 4; i++) {
        #pragma unroll
        for (int j = 0; j < 8; j++) {
            int r0 = m0 + wm + i * 16 + lr;
            int cc = n0 + wn + j * 8 + lc * 2;
            float x0 = acc[i][j][0], x1 = acc[i][j][1];
            float x2 = acc[i][j][2], x3 = acc[i][j][3];
            if (EPI == 1) {
                __half* Ch = (__half*)Cv;
                *(__half2*)(Ch + (size_t)r0 * N + cc) =
                    __floats2half2_rn(gelu_exact(x0), gelu_exact(x1));
                *(__half2*)(Ch + (size_t)(r0 + 8) * N + cc) =
                    __floats2half2_rn(gelu_exact(x2), gelu_exact(x3));
            } else if (EPI == 3) {
                __half* Ch = (__half*)Cv;
                *(__half2*)(Ch + (size_t)r0 * N + cc)       = __floats2half2_rn(x0, x1);
                *(__half2*)(Ch + (size_t)(r0 + 8) * N + cc) = __floats2half2_rn(x2, x3);
            } else {
                float* Cf = (float*)Cv;
                if (EPI == 2) {
                    size_t i0 = (size_t)r0 * N + cc;
                    size_t i1 = (size_t)(r0 + 8) * N + cc;
                    float2 a0 = *(const float2*)(R1 + i0);
                    float2 a1 = *(const float2*)(R1 + i1);
                    float2 d0 = *(const float2*)(R2 + i0);
                    float2 d1 = *(const float2*)(R2 + i1);
                    x0 += a0.x + d0.x; x1 += a0.y + d0.y;
                    x2 += a1.x + d1.x; x3 += a1.y + d1.y;
                }
                *(float2*)(Cf + (size_t)r0 * N + cc)       = make_float2(x0, x1);
                *(float2*)(Cf + (size_t)(r0 + 8) * N + cc) = make_float2(x2, x3);
            }
        }
    }
}

// Single-job GEMM
template <int EPI>
__global__ void __launch_bounds__(256, 1)
mma_gemm_kernel(const __half* __restrict__ A, const __half* __restrict__ Bt,
                void* __restrict__ Cv, int K, int N,
                const float* __restrict__ R1, const float* __restrict__ R2)
{
    extern __shared__ __half gsm[];
    gemm_core<EPI>(A, Bt, Cv, K, N, R1, R2, blockIdx.x * 256, blockIdx.y * 128, gsm);
}

// Dual-job GEMM (independent jobs, same M=2048): flattened 1D grid.
template <int EPI0, int EPI1>
__global__ void __launch_bounds__(256, 1)
mma_gemm_dual(const __half* __restrict__ A0, const __half* __restrict__ B0,
              void* __restrict__ C0, int K0, int N0, int nx0,
              const __half* __restrict__ A1, const __half* __restrict__ B1,
              void* __restrict__ C1, int K1, int N1)
{
    extern __shared__ __half gsm[];
    int idx = blockIdx.x;
    if (idx < nx0) {
        gemm_core<EPI0>(A0, B0, C0, K0, N0, nullptr, nullptr,
                        (idx & 7) * 256, (idx >> 3) * 128, gsm);
    } else {
        idx -= nx0;
        gemm_core<EPI1>(A1, B1, C1, K1, N1, nullptr, nullptr,
                        (idx & 7) * 256, (idx >> 3) * 128, gsm);
    }
}

// ---------------------------------------------------------------------------
// RoPE + head split (fp16 in/out)
// ---------------------------------------------------------------------------
__global__ void __launch_bounds__(128)
rope_kernel(const __half* __restrict__ qkv,
            const float* __restrict__ sint, const float* __restrict__ cost,
            const int* __restrict__ pos_ids,
            __half* __restrict__ Qo, __half* __restrict__ Ko, __half* __restrict__ Vo)
{
    int d = threadIdx.x;
    int idx = blockIdx.x;
    int kvh = idx % NKV; idx /= NKV;
    int s = idx % Sq;
    int b = idx / Sq;

    int pos = pos_ids[b * Sq + s];
    float sn = sint[pos * HD + d];
    float cs = cost[pos * HD + d];
    int dro = (d < 64) ? (d + 64) : (d - 64);
    float sgn = (d < 64) ? -1.f : 1.f;

    const __half* base = qkv + (size_t)(b * Sq + s) * QKVW + kvh * (Gq + 2) * HD;

    float kx = __half2float(base[Gq * HD + d]);
    float ko = __half2float(base[Gq * HD + dro]);
    size_t kvidx = ((size_t)(b * NKV + kvh) * Sq + s) * HD + d;
    Ko[kvidx] = __float2half_rn(kx * cs + sgn * ko * sn);
    Vo[kvidx] = base[(Gq + 1) * HD + d];

    #pragma unroll
    for (int g = 0; g < Gq; g++) {
        int h = kvh * Gq + g;
        float qx = __half2float(base[g * HD + d]);
        float qo = __half2float(base[g * HD + dro]);
        Qo[((size_t)(b * NH + h) * Sq + s) * HD + d] =
            __float2half_rn(qx * cs + sgn * qo * sn);
    }
}

// ---------------------------------------------------------------------------
// Tensor-core flash attention, cp.async double-buffered K/V pipeline.
// ---------------------------------------------------------------------------
#define VROW 136
#define KVSZ (64 * VROW)
#define ATTN_SMEM (5 * KVSZ * 2 + 2 * 64 * 4)

__device__ __forceinline__ void kv_load(const __half* __restrict__ Kb,
                                        const __half* __restrict__ Vb,
                                        __half* Ks, __half* Vs, int k0, int t)
{
    #pragma unroll
    for (int j = 0; j < 8; j++) {
        int i = t + j * 128;
        int r = i >> 4, c8 = (i & 15) * 8;
        CP_ASYNC16(smem_u32(&Ks[r * VROW + c8]), Kb + (size_t)(k0 + r) * HD + c8);
        CP_ASYNC16(smem_u32(&Vs[r * VROW + c8]), Vb + (size_t)(k0 + r) * HD + c8);
    }
    CP_COMMIT();
}

__global__ void __launch_bounds__(128)
attn_kernel(const __half* __restrict__ Q, const __half* __restrict__ Kg,
            const __half* __restrict__ Vg, const int* __restrict__ amask,
            __half* __restrict__ ctx)
{
    extern __shared__ __half asmem[];
    __half* Qs = asmem;
    __half* Kst0 = asmem + KVSZ;
    __half* Vst0 = asmem + 2 * KVSZ;
    __half* Kst1 = asmem + 3 * KVSZ;
    __half* Vst1 = asmem + 4 * KVSZ;
    int* smask = (int*)(asmem + 5 * KVSZ);   // [2][64]

    int t = threadIdx.x, lane = t & 31, w = t >> 5;
    int q0 = blockIdx.x * 64, h = blockIdx.y, b = blockIdx.z, kv = h >> 2;
    int lr = lane >> 2, lc = lane & 3;

    const __half* Qb = Q  + ((size_t)(b * NH  + h ) * Sq + q0) * HD;
    const __half* Kb = Kg + ((size_t)(b * NKV + kv) * Sq) * HD;
    const __half* Vb = Vg + ((size_t)(b * NKV + kv) * Sq) * HD;

    const int nc = q0 / 64 + 1;

    kv_load(Kb, Vb, Kst0, Vst0, 0, t);
    if (t < 64) smask[t] = amask[b * Sq + t];

    for (int i = t; i < 64 * 16; i += 128) {
        int r = i >> 4, c8 = (i & 15) * 8;
        *(uint4*)&Qs[r * VROW + c8] = *(const uint4*)(Qb + (size_t)r * HD + c8);
    }
    __syncthreads();

    uint32_t qf[8][4];
    #pragma unroll
    for (int kk = 0; kk < 8; kk++) {
        uint32_t addr = smem_u32(&Qs[(16 * w + (lane & 15)) * VROW + kk * 16 + (lane >> 4) * 8]);
        LDSM_X4(qf[kk][0], qf[kk][1], qf[kk][2], qf[kk][3], addr);
    }

    float oacc[16][4];
    #pragma unroll
    for (int i = 0; i < 16; i++)
        #pragma unroll
        for (int q = 0; q < 4; q++) oacc[i][q] = 0.f;

    float m0r = -1e30f, m1r = -1e30f, l0r = 0.f, l1r = 0.f;
    int qg1 = q0 + 16 * w + lr, qg2 = qg1 + 8;

    for (int c = 0; c < nc; c++) {
        int st = c & 1;
        __half* Ks = st ? Kst1 : Kst0;
        __half* Vs = st ? Vst1 : Vst0;
        const int* msk = smask + st * 64;
        int k0 = c * 64;

        if (c + 1 < nc) {
            kv_load(Kb, Vb, st ? Kst0 : Kst1, st ? Vst0 : Vst1, k0 + 64, t);
            if (t < 64) smask[(st ^ 1) * 64 + t] = amask[b * Sq + k0 + 64 + t];
            asm volatile("cp.async.wait_group 1;" ::: "memory");
        } else {
            asm volatile("cp.async.wait_group 0;" ::: "memory");
        }
        __syncthreads();

        float sacc[8][4];
        #pragma unroll
        for (int j = 0; j < 8; j++)
            #pragma unroll
            for (int q = 0; q < 4; q++) sacc[j][q] = 0.f;

        #pragma unroll
        for (int kk = 0; kk < 8; kk++) {
            #pragma unroll
            for (int jj = 0; jj < 4; jj++) {
                uint32_t addr = smem_u32(&Ks[(16 * jj + (lane & 7) + (lane >> 4) * 8) * VROW
                                             + kk * 16 + ((lane >> 3) & 1) * 8]);
                uint32_t b0, b1, b2, b3;
                LDSM_X4(b0, b1, b2, b3, addr);
                mma_f16(sacc[2 * jj],     qf[kk][0], qf[kk][1], qf[kk][2], qf[kk][3], b0, b1);
                mma_f16(sacc[2 * jj + 1], qf[kk][0], qf[kk][1], qf[kk][2], qf[kk][3], b2, b3);
            }
        }

        float mn0 = m0r, mn1 = m1r;
        #pragma unroll
        for (int j = 0; j < 8; j++) {
            int kg = k0 + 8 * j + 2 * lc;
            bool ma = msk[8 * j + 2 * lc] > 0;
            bool mb = msk[8 * j + 2 * lc + 1] > 0;
            float s0 = (ma && kg     <= qg1) ? sacc[j][0] * ATTN_SCALE : -1e30f;
            float s1 = (mb && kg + 1 <= qg1) ? sacc[j][1] * ATTN_SCALE : -1e30f;
            float s2 = (ma && kg     <= qg2) ? sacc[j][2] * ATTN_SCALE : -1e30f;
            float s3 = (mb && kg + 1 <= qg2) ? sacc[j][3] * ATTN_SCALE : -1e30f;
            sacc[j][0] = s0; sacc[j][1] = s1; sacc[j][2] = s2; sacc[j][3] = s3;
            mn0 = fmaxf(mn0, fmaxf(s0, s1));
            mn1 = fmaxf(mn1, fmaxf(s2, s3));
        }
        mn0 = fmaxf(mn0, __shfl_xor_sync(0xFFFFFFFFu, mn0, 1));
        mn0 = fmaxf(mn0, __shfl_xor_sync(0xFFFFFFFFu, mn0, 2));
        mn1 = fmaxf(mn1, __shfl_xor_sync(0xFFFFFFFFu, mn1, 1));
        mn1 = fmaxf(mn1, __shfl_xor_sync(0xFFFFFFFFu, mn1, 2));

        float cf0 = __expf(m0r - mn0);
        float cf1 = __expf(m1r - mn1);
        m0r = mn0; m1r = mn1;

        uint32_t pf[8][2];
        float la0 = 0.f, la1 = 0.f;
        #pragma unroll
        for (int j = 0; j < 8; j++) {
            float p0 = __expf(sacc[j][0] - mn0);
            float p1 = __expf(sacc[j][1] - mn0);
            float p2 = __expf(sacc[j][2] - mn1);
            float p3 = __expf(sacc[j][3] - mn1);
            la0 += p0 + p1; la1 += p2 + p3;
            pf[j][0] = h2u(p0, p1);
            pf[j][1] = h2u(p2, p3);
        }
        la0 += __shfl_xor_sync(0xFFFFFFFFu, la0, 1);
        la0 += __shfl_xor_sync(0xFFFFFFFFu, la0, 2);
        la1 += __shfl_xor_sync(0xFFFFFFFFu, la1, 1);
        la1 += __shfl_xor_sync(0xFFFFFFFFu, la1, 2);
        l0r = l0r * cf0 + la0;
        l1r = l1r * cf1 + la1;

        #pragma unroll
        for (int dt = 0; dt < 16; dt++) {
            oacc[dt][0] *= cf0; oacc[dt][1] *= cf0;
            oacc[dt][2] *= cf1; oacc[dt][3] *= cf1;
        }

        #pragma unroll
        for (int t4 = 0; t4 < 4; t4++) {
            uint32_t a0 = pf[2 * t4][0], a1 = pf[2 * t4][1];
            uint32_t a2 = pf[2 * t4 + 1][0], a3 = pf[2 * t4 + 1][1];
            #pragma unroll
            for (int jn2 = 0; jn2 < 8; jn2++) {
                uint32_t addr = smem_u32(&Vs[(16 * t4 + (lane & 7) + ((lane >> 3) & 1) * 8) * VROW
                                             + 16 * jn2 + (lane >> 4) * 8]);
                uint32_t v0, v1, v2, v3;
                LDSM_X4T(v0, v1, v2, v3, addr);
                mma_f16(oacc[2 * jn2],     a0, a1, a2, a3, v0, v1);
                mma_f16(oacc[2 * jn2 + 1], a0, a1, a2, a3, v2, v3);
            }
        }
        __syncthreads();
    }

    float inv0 = 1.f / l0r, inv1 = 1.f / l1r;
    int row1 = q0 + 16 * w + lr, row2 = row1 + 8;
    #pragma unroll
    for (int jn = 0; jn < 16; jn++) {
        int col = h * HD + 8 * jn + 2 * lc;
        *(__half2*)&ctx[(size_t)(b * Sq + row1) * Hq + col] =
            __floats2half2_rn(oacc[jn][0] * inv0, oacc[jn][1] * inv0);
        *(__half2*)&ctx[(size_t)(b * Sq + row2) * Hq + col] =
            __floats2half2_rn(oacc[jn][2] * inv1, oacc[jn][3] * inv1);
    }
}

// ---------------------------------------------------------------------------
// Launch
// ---------------------------------------------------------------------------
extern "C" void kernel_launch(void* const* d_in, const int* in_sizes, int n_in,
                              void* d_out, int out_size)
{
    const float* hidden  = (const float*)d_in[0];
    const float* w_qkv   = (const float*)d_in[1];
    const float* w_dense = (const float*)d_in[2];
    const float* ln_a_s  = (const float*)d_in[3];
    const float* ln_a_b  = (const float*)d_in[4];
    const float* ln_m_s  = (const float*)d_in[5];
    const float* ln_m_b  = (const float*)d_in[6];
    const float* w_fc    = (const float*)d_in[7];
    const float* w_out   = (const float*)d_in[8];
    const float* sin_tab = (const float*)d_in[9];
    const float* cos_tab = (const float*)d_in[10];
    const int*   amask   = (const int*)d_in[11];
    const int*   pos_ids = (const int*)d_in[12];
    float* out = (float*)d_out;

    __half *p_attn_in, *p_mlp_in, *p_qkv, *p_q, *p_k, *p_v, *p_ctx, *p_fc;
    __half *p_wqkv, *p_wdense, *p_wfc, *p_wout;
    float *p_attn_out;
    cudaGetSymbolAddress((void**)&p_attn_in,  g_attn_in);
    cudaGetSymbolAddress((void**)&p_mlp_in,   g_mlp_in);
    cudaGetSymbolAddress((void**)&p_qkv,      g_qkv);
    cudaGetSymbolAddress((void**)&p_q,        g_q);
    cudaGetSymbolAddress((void**)&p_k,        g_k);
    cudaGetSymbolAddress((void**)&p_v,        g_v);
    cudaGetSymbolAddress((void**)&p_ctx,      g_ctx);
    cudaGetSymbolAddress((void**)&p_attn_out, g_attn_out);
    cudaGetSymbolAddress((void**)&p_fc,       g_fc);
    cudaGetSymbolAddress((void**)&p_wqkv,     g_wqkv_t);
    cudaGetSymbolAddress((void**)&p_wdense,   g_wdense_t);
    cudaGetSymbolAddress((void**)&p_wfc,      g_wfc_t);
    cudaGetSymbolAddress((void**)&p_wout,     g_wout_t);

    cudaFuncSetAttribute(mma_gemm_kernel<2>, cudaFuncAttributeMaxDynamicSharedMemorySize, GEMM_SMEM);
    cudaFuncSetAttribute(mma_gemm_kernel<3>, cudaFuncAttributeMaxDynamicSharedMemorySize, GEMM_SMEM);
    cudaFuncSetAttribute((const void*)mma_gemm_dual<0, 1>, cudaFuncAttributeMaxDynamicSharedMemorySize, GEMM_SMEM);
    cudaFuncSetAttribute(attn_kernel, cudaFuncAttributeMaxDynamicSharedMemorySize, ATTN_SMEM);

    // 0. merged transpose + fp16 round of all 4 weights
    transpose4_kernel<<<TR_NB3, 256>>>(w_qkv, p_wqkv, w_dense, p_wdense,
                                       w_fc, p_wfc, w_out, p_wout);

    // 1. parallel layernorms (fp16 outputs)
    ln_dual_kernel<<<Mrows, 256>>>(hidden, ln_a_s, ln_a_b, ln_m_s, ln_m_b,
                                   p_attn_in, p_mlp_in);

    // 2. qkv projection (fp16 out)
    mma_gemm_kernel<3><<<dim3(Mrows/256, QKVW/128), 256, GEMM_SMEM>>>(
        p_attn_in, p_wqkv, p_qkv, Hq, QKVW, nullptr, nullptr);

    // 3. rope + head split (fp16)
    rope_kernel<<<Bq * Sq * NKV, 128>>>(p_qkv, sin_tab, cos_tab, pos_ids,
                                        p_q, p_k, p_v);

    // 4. tensor-core attention, pipelined (ctx fp16)
    attn_kernel<<<dim3(Sq / 64, NH, Bq), 128, ATTN_SMEM>>>(
        p_q, p_k, p_v, amask, p_ctx);

    // 5+6. dense projection (f32 out) + MLP fc with GELU (fp16 out), merged
    {
        int nx_dense = (Mrows / 256) * (Hq / 128);   // 256
        int nx_fc    = (Mrows / 256) * (FF / 128);   // 1024
        mma_gemm_dual<0, 1><<<nx_dense + nx_fc, 256, GEMM_SMEM>>>(
            p_ctx,    p_wdense, p_attn_out, Hq, Hq, nx_dense,
            p_mlp_in, p_wfc,    p_fc,       Hq, FF);
    }

    // 7. MLP out + parallel residual -> d_out (f32)
    mma_gemm_kernel<2><<<dim3(Mrows/256, Hq/128), 256, GEMM_SMEM>>>(
        p_fc, p_wout, out, FF, Hq, hidden, p_attn_out);
}